// round 1
// baseline (speedup 1.0000x reference)
#include <cuda_runtime.h>
#include <cuda_bf16.h>

// BSplineKAN: out[b,c] = sum_i cp[c,i] * N_{i,3}(clamp(x[b,c],-.99,.99))
// with uniform knots linspace(-1,1,12), h = 2/11.
//
// On each knot interval j (0..10) the spline output is a single cubic in x.
// Precompute coeff[c][j][0..3] once (exact, double-precision symbolic
// Cox-de Boor over polynomials), then the hot kernel is a table lookup +
// 3-FMA Horner per element. HBM-bound: 134 MB traffic.

#define NUM_CH 64
#define NUM_CP 8
#define NUM_INTERVALS 11   // 12 knots -> 11 degree-0 intervals

__device__ float4 g_coeff[NUM_CH * NUM_INTERVALS];

// -------- precompute: one block --------
__global__ void precompute_coeff_kernel(const float* __restrict__ cp) {
    // basis polynomials restricted to interval j:
    // bp[j][i][d] = coeff of x^d of N_{i,3} on interval j (i = 0..7)
    __shared__ double bp[NUM_INTERVALS][NUM_CP][4];
    const int tid = threadIdx.x;
    const double h = 2.0 / 11.0;

    if (tid < NUM_INTERVALS) {
        const int j = tid;
        // P[i][d]: polynomial for basis index i at current degree.
        double P[11][4];
        for (int i = 0; i < 11; i++)
            for (int d = 0; d < 4; d++) P[i][d] = 0.0;
        P[j][0] = 1.0;   // degree 0: indicator of interval j

        for (int k = 1; k <= 3; k++) {
            double newP[11][4];
            const int nlen = 11 - k;   // array length at degree k
            for (int i = 0; i < nlen; i++) {
                const double ti   = -1.0 + i * h;
                const double tik1 = -1.0 + (i + k + 1) * h;
                const double inv  = 1.0 / (k * h);
                double r[4] = {0.0, 0.0, 0.0, 0.0};
                // (x - ti)*inv * P[i]  +  (tik1 - x)*inv * P[i+1]
                for (int d = 0; d < 4; d++) {
                    if (d < 3) r[d + 1] += inv * P[i][d];
                    r[d] += inv * (-ti) * P[i][d];
                    r[d] += inv * tik1 * P[i + 1][d];
                    if (d < 3) r[d + 1] -= inv * P[i + 1][d];
                }
                for (int d = 0; d < 4; d++) newP[i][d] = r[d];
            }
            for (int i = 0; i < nlen; i++)
                for (int d = 0; d < 4; d++) P[i][d] = newP[i][d];
            for (int i = nlen; i < 11; i++)        // clear stale entries
                for (int d = 0; d < 4; d++) P[i][d] = 0.0;
        }
        for (int i = 0; i < NUM_CP; i++)
            for (int d = 0; d < 4; d++) bp[j][i][d] = P[i][d];
    }
    __syncthreads();

    // combine with control points: coeff[c][j][d] = sum_i cp[c,i]*bp[j][i][d]
    for (int idx = tid; idx < NUM_CH * NUM_INTERVALS; idx += blockDim.x) {
        const int c = idx / NUM_INTERVALS;
        const int j = idx % NUM_INTERVALS;
        double acc[4] = {0.0, 0.0, 0.0, 0.0};
        for (int i = 0; i < NUM_CP; i++) {
            const double w = (double)cp[c * NUM_CP + i];
            for (int d = 0; d < 4; d++) acc[d] += w * bp[j][i][d];
        }
        g_coeff[idx] = make_float4((float)acc[0], (float)acc[1],
                                   (float)acc[2], (float)acc[3]);
    }
}

// -------- hot kernel: grid-stride over float4 --------
__global__ __launch_bounds__(256)
void kan_eval_kernel(const float4* __restrict__ x4,
                     float4* __restrict__ out4, int nvec) {
    __shared__ float4 sco[NUM_CH * NUM_INTERVALS];   // 11,264 B
    for (int i = threadIdx.x; i < NUM_CH * NUM_INTERVALS; i += blockDim.x)
        sco[i] = g_coeff[i];
    __syncthreads();

    const int stride = gridDim.x * blockDim.x;
    for (int v = blockIdx.x * blockDim.x + threadIdx.x; v < nvec; v += stride) {
        float4 xv = x4[v];
        // element idx = 4*v + s; channel = (4*v + s) & 63; 4 | 64 so no wrap
        const int cbase = (v << 2) & 63;

        float xin[4] = {xv.x, xv.y, xv.z, xv.w};
        float yo[4];
#pragma unroll
        for (int s = 0; s < 4; s++) {
            float xx = fminf(fmaxf(xin[s], -0.99f), 0.99f);
            float u = (xx + 1.0f) * 5.5f;          // 1/h = 5.5
            int j = (int)u;                         // u in [0.055, 10.945]
            j = max(0, min(j, NUM_INTERVALS - 1));
            float4 co = sco[(cbase + s) * NUM_INTERVALS + j];
            yo[s] = fmaf(fmaf(fmaf(co.w, xx, co.z), xx, co.y), xx, co.x);
        }
        out4[v] = make_float4(yo[0], yo[1], yo[2], yo[3]);
    }
}

extern "C" void kernel_launch(void* const* d_in, const int* in_sizes, int n_in,
                              void* d_out, int out_size) {
    const float* x  = (const float*)d_in[0];           // [262144, 64]
    const float* cp = (const float*)d_in[1];           // [64, 8]
    float* out = (float*)d_out;

    const int n = in_sizes[0];            // total elements (B*C)
    const int nvec = n >> 2;              // float4 count (n % 4 == 0)

    precompute_coeff_kernel<<<1, 256>>>(cp);

    const int threads = 256;
    const int blocks = 1184;              // 148 SMs x 8 CTAs, one wave
    kan_eval_kernel<<<blocks, threads>>>((const float4*)x, (float4*)out, nvec);
}

// round 2
// speedup vs baseline: 1.8705x; 1.8705x over previous
#include <cuda_runtime.h>
#include <cuda_bf16.h>

// BSplineKAN, uniform knots linspace(-1,1,12), order 3, h = 2/11.
//
// On knot interval j (u = (x+1)/h in [j, j+1), t = u - j), the output is
//   S_c(x) = sum_{k=0..3, 0 <= j-3+k <= 7} cp[c][j-3+k] * w_k(t)
// with the standard uniform cubic B-spline weights
//   w0 = (1 -3t +3t^2 -t^3)/6, w1 = (4 -6t^2 +3t^3)/6,
//   w2 = (1 +3t +3t^2 -3t^3)/6, w3 = t^3/6.
// Per (channel, interval) this collapses to ONE cubic in t. Each block
// builds the 64x11 float4 coefficient table in a cheap prologue (16 FMAs
// per entry from the constant matrix), then the hot loop is:
//   clamp -> j,t -> one conflict-free LDS.128 -> 3-FMA Horner.
//
// Swizzle: lane l's channels are 4*(l&15)+s (fixed). Layout index
// j*64 + (((c&3)<<4) | (c>>2)) makes each 8-lane LDS.128 phase start at
// word 4*(l mod 8) mod 32 -> tiles all 32 banks, zero conflicts, for ANY
// data-dependent j (j contributes 256 words = 0 mod 32).

#define NUM_CH 64
#define NUM_CP 8
#define NUM_INTERVALS 11

__global__ __launch_bounds__(256)
void kan_fused_kernel(const float4* __restrict__ x4,
                      const float* __restrict__ cp,
                      float4* __restrict__ out4, int nvec) {
    __shared__ float4 sco[NUM_INTERVALS * NUM_CH];   // 11,264 B, swizzled

    // ---- prologue: build t-polynomial coeff table (all blocks, ~100 cyc) ----
    // M[k][d] = coeff of t^d in w_k, times 1/6 folded in.
    const float M[4][4] = {
        { 1.f/6.f, -3.f/6.f,  3.f/6.f, -1.f/6.f },
        { 4.f/6.f,  0.f,     -6.f/6.f,  3.f/6.f },
        { 1.f/6.f,  3.f/6.f,  3.f/6.f, -3.f/6.f },
        { 0.f,      0.f,      0.f,      1.f/6.f },
    };
    for (int idx = threadIdx.x; idx < NUM_INTERVALS * NUM_CH; idx += blockDim.x) {
        const int j = idx >> 6;          // 0..10
        const int c = idx & 63;
        float a0 = 0.f, a1 = 0.f, a2 = 0.f, a3 = 0.f;
#pragma unroll
        for (int k = 0; k < 4; k++) {
            const int i = j - 3 + k;
            if (i >= 0 && i < NUM_CP) {
                const float p = __ldg(&cp[c * NUM_CP + i]);
                a0 = fmaf(p, M[k][0], a0);
                a1 = fmaf(p, M[k][1], a1);
                a2 = fmaf(p, M[k][2], a2);
                a3 = fmaf(p, M[k][3], a3);
            }
        }
        const int slot = ((c & 3) << 4) | (c >> 2);   // bank-tiling swizzle
        sco[(j << 6) + slot] = make_float4(a0, a1, a2, a3);
    }
    __syncthreads();

    // ---- hot loop ----
    // channel base depends only on tid: cbase = (4*tid) & 63 (grid stride
    // in elements is a multiple of 64).
    const int cbase = (threadIdx.x << 2) & 63;
    int slot_s[4];
#pragma unroll
    for (int s = 0; s < 4; s++) {
        const int c = cbase + s;                      // s<4, cbase mult of 4
        slot_s[s] = ((c & 3) << 4) | (c >> 2);
    }

    const int stride = gridDim.x * blockDim.x;
    for (int v = blockIdx.x * blockDim.x + threadIdx.x; v < nvec; v += stride) {
        const float4 xv = x4[v];
        float xin[4] = {xv.x, xv.y, xv.z, xv.w};
        float yo[4];
#pragma unroll
        for (int s = 0; s < 4; s++) {
            float xx = fminf(fmaxf(xin[s], -0.99f), 0.99f);
            float u  = (xx + 1.0f) * 5.5f;            // (x+1)/h, h = 2/11
            int   j  = (int)u;
            j = max(0, min(j, NUM_INTERVALS - 1));
            float t  = u - (float)j;
            const float4 co = sco[(j << 6) + slot_s[s]];
            yo[s] = fmaf(fmaf(fmaf(co.w, t, co.z), t, co.y), t, co.x);
        }
        out4[v] = make_float4(yo[0], yo[1], yo[2], yo[3]);
    }
}

extern "C" void kernel_launch(void* const* d_in, const int* in_sizes, int n_in,
                              void* d_out, int out_size) {
    const float* x  = (const float*)d_in[0];          // [262144, 64]
    const float* cp = (const float*)d_in[1];          // [64, 8]
    float* out = (float*)d_out;

    const int n = in_sizes[0];                        // B*C elements
    const int nvec = n >> 2;                          // float4 count

    const int threads = 256;
    const int blocks = 1184;                          // 148 SMs x 8 CTAs
    kan_fused_kernel<<<blocks, threads>>>((const float4*)x, cp,
                                          (float4*)out, nvec);
}

// round 4
// speedup vs baseline: 1.9094x; 1.0208x over previous
#include <cuda_runtime.h>
#include <cuda_bf16.h>

// BSplineKAN, uniform knots linspace(-1,1,12), order 3, h = 2/11.
//
// Per (channel, knot-interval) the spline output collapses to ONE cubic in
// local coordinate t (uniform cubic B-spline matrix form). Each block builds
// the 64x11 float4 coeff table in a cheap register prologue, then the hot
// loop is: clamp -> j,t -> conflict-free LDS.128 -> 3-FMA Horner.
//
// Round-3 change: 2 float4s in flight per thread (block-striped pair v,
// v+256) so both LDG.128s issue back-to-back -> MLP 2, halving exposed
// DRAM latency. j-clamp dropped (x-clamp already bounds u to [0.055,10.945]).
//
// Swizzle: lane l's channels are 4*(l&15)+s (fixed). Slot index
// (((c&3)<<4)|(c>>2)) tiles all 32 banks within each 8-lane LDS.128 phase
// for ANY data-dependent j (j contributes 256 words = 0 mod 32).

#define NUM_CH 64
#define NUM_CP 8
#define NUM_INTERVALS 11

__global__ __launch_bounds__(256)
void kan_fused_kernel(const float4* __restrict__ x4,
                      const float* __restrict__ cp,
                      float4* __restrict__ out4, int nvec) {
    __shared__ float4 sco[NUM_INTERVALS * NUM_CH];   // 11,264 B, swizzled

    // ---- prologue: t-polynomial coeff table (uniform B-spline matrix /6) ----
    const float M[4][4] = {
        { 1.f/6.f, -3.f/6.f,  3.f/6.f, -1.f/6.f },
        { 4.f/6.f,  0.f,     -6.f/6.f,  3.f/6.f },
        { 1.f/6.f,  3.f/6.f,  3.f/6.f, -3.f/6.f },
        { 0.f,      0.f,      0.f,      1.f/6.f },
    };
    for (int idx = threadIdx.x; idx < NUM_INTERVALS * NUM_CH; idx += blockDim.x) {
        const int j = idx >> 6;          // 0..10
        const int c = idx & 63;
        float a0 = 0.f, a1 = 0.f, a2 = 0.f, a3 = 0.f;
#pragma unroll
        for (int k = 0; k < 4; k++) {
            const int i = j - 3 + k;
            if (i >= 0 && i < NUM_CP) {
                const float p = __ldg(&cp[c * NUM_CP + i]);
                a0 = fmaf(p, M[k][0], a0);
                a1 = fmaf(p, M[k][1], a1);
                a2 = fmaf(p, M[k][2], a2);
                a3 = fmaf(p, M[k][3], a3);
            }
        }
        const int slot = ((c & 3) << 4) | (c >> 2);   // bank-tiling swizzle
        sco[(j << 6) + slot] = make_float4(a0, a1, a2, a3);
    }
    __syncthreads();

    // ---- hot loop: 2 float4s per thread per iteration ----
    // Channel base for BOTH vectors: (4*tid)&63 (pair offset 256 float4s
    // = 1024 elements = 0 mod 64; grid stride 512*gridDim also 0 mod 64).
    const int cbase = (threadIdx.x << 2) & 63;
    int slot_s[4];
#pragma unroll
    for (int s = 0; s < 4; s++) {
        const int c = cbase + s;
        slot_s[s] = ((c & 3) << 4) | (c >> 2);
    }

    const int chunk  = 2 * blockDim.x;                // 512 float4s per block-iter
    const int stride = gridDim.x * chunk;

    for (int base = blockIdx.x * chunk + threadIdx.x; base < nvec; base += stride) {
        const int v0 = base;
        const int v1 = base + (int)blockDim.x;
        const bool has1 = (v1 < nvec);

        // front-batch both global loads
        float4 xa = x4[v0];
        float4 xb = has1 ? x4[v1] : make_float4(0.f, 0.f, 0.f, 0.f);

        float xin[8] = {xa.x, xa.y, xa.z, xa.w, xb.x, xb.y, xb.z, xb.w};
        float yo[8];
#pragma unroll
        for (int s = 0; s < 8; s++) {
            float xx = fminf(fmaxf(xin[s], -0.99f), 0.99f);
            float u  = fmaf(xx, 5.5f, 5.5f);          // (x+1)*5.5, u in [0.055,10.945]
            int   j  = (int)u;                        // floor, guaranteed 0..10
            float t  = u - (float)j;
            const float4 co = sco[(j << 6) + slot_s[s & 3]];
            yo[s] = fmaf(fmaf(fmaf(co.w, t, co.z), t, co.y), t, co.x);
        }
        out4[v0] = make_float4(yo[0], yo[1], yo[2], yo[3]);
        if (has1)
            out4[v1] = make_float4(yo[4], yo[5], yo[6], yo[7]);
    }
}

extern "C" void kernel_launch(void* const* d_in, const int* in_sizes, int n_in,
                              void* d_out, int out_size) {
    const float* x  = (const float*)d_in[0];          // [262144, 64]
    const float* cp = (const float*)d_in[1];          // [64, 8]
    float* out = (float*)d_out;

    const int n = in_sizes[0];                        // B*C elements
    const int nvec = n >> 2;                          // float4 count

    const int threads = 256;
    const int blocks = 1184;                          // 148 SMs x 8 CTAs
    kan_fused_kernel<<<blocks, threads>>>((const float4*)x, cp,
                                          (float4*)out, nvec);
}